// round 1
// baseline (speedup 1.0000x reference)
#include <cuda_runtime.h>
#include <cuda_bf16.h>

// Problem constants (B=4, S=2048, D=16, HEADS=16, HEAD_SIZE=1)
#define BB   4
#define SS   2048
#define DD   16
#define NPAIR (BB * DD)          // 64 (b,h) pairs
#define LOG2E 1.4426950408889634f

// Scratch (allocation-free rule: __device__ globals)
__device__ float g_q[NPAIR * SS];
__device__ float g_k[NPAIR * SS];
__device__ float g_v[NPAIR * SS];
__device__ float g_att[NPAIR * SS];

// ---------------------------------------------------------------------------
// Kernel A: qkv = x @ w_qkv + b_qkv, scattered into pair-major q/k/v arrays.
// One thread per (b,s) row. 32 blocks x 256 threads.
// ---------------------------------------------------------------------------
__global__ void qkv_kernel(const float* __restrict__ x,
                           const float* __restrict__ w,   // [16, 48] row-major
                           const float* __restrict__ bias) // [48]
{
    __shared__ float sw[DD * 3 * DD];   // 768
    __shared__ float sb[3 * DD];        // 48
    int t = threadIdx.x;
    for (int i = t; i < DD * 3 * DD; i += blockDim.x) sw[i] = w[i];
    if (t < 3 * DD) sb[t] = bias[t];
    __syncthreads();

    int r = blockIdx.x * blockDim.x + t;        // 0 .. B*S-1
    if (r >= BB * SS) return;
    int b = r >> 11;          // r / 2048
    int s = r & (SS - 1);

    // load x row (16 floats) with float4
    float xr[DD];
    const float4* xp = reinterpret_cast<const float4*>(x + r * DD);
    #pragma unroll
    for (int q4 = 0; q4 < 4; q4++) {
        float4 v4 = xp[q4];
        xr[q4 * 4 + 0] = v4.x; xr[q4 * 4 + 1] = v4.y;
        xr[q4 * 4 + 2] = v4.z; xr[q4 * 4 + 3] = v4.w;
    }

    #pragma unroll
    for (int c = 0; c < 3 * DD; c++) {
        float acc = sb[c];
        #pragma unroll
        for (int d = 0; d < DD; d++)
            acc = fmaf(xr[d], sw[d * 3 * DD + c], acc);
        int h = c & (DD - 1);                    // c % 16
        int pair = b * DD + h;
        if (c < DD)           g_q[pair * SS + s] = acc;
        else if (c < 2 * DD)  g_k[pair * SS + s] = acc;
        else                  g_v[pair * SS + s] = acc;
    }
}

// ---------------------------------------------------------------------------
// Kernel B: scalar-head causal attention per (b,h) pair.
// grid (64 pairs, 8 slices), 256 threads (8 warps). Warp gw = slice*8+w
// handles rows i = gw, gw+64, ...  k,v live in SMEM.
// ---------------------------------------------------------------------------
#define NSLICE 8
#define BWARPS 8

__global__ void attn_kernel(const float* __restrict__ gq,
                            const float* __restrict__ gk,
                            const float* __restrict__ gv,
                            float* __restrict__ gatt)
{
    __shared__ float sk[SS];
    __shared__ float sv[SS];
    __shared__ float redmx[BWARPS], redmn[BWARPS];

    int pair  = blockIdx.x;
    int slice = blockIdx.y;
    int t = threadIdx.x, lane = t & 31, w = t >> 5;

    const float* kp = gk + pair * SS;
    const float* vp = gv + pair * SS;
    const float* qp = gq + pair * SS;

    float lmax = -3.4e38f, lmin = 3.4e38f;
    for (int j = t; j < SS; j += 256) {
        float kv = kp[j];
        sk[j] = kv;
        sv[j] = vp[j];
        lmax = fmaxf(lmax, kv);
        lmin = fminf(lmin, kv);
    }
    #pragma unroll
    for (int off = 16; off; off >>= 1) {
        lmax = fmaxf(lmax, __shfl_xor_sync(0xffffffffu, lmax, off));
        lmin = fminf(lmin, __shfl_xor_sync(0xffffffffu, lmin, off));
    }
    if (lane == 0) { redmx[w] = lmax; redmn[w] = lmin; }
    __syncthreads();

    float kmax = redmx[0], kmin = redmn[0];
    #pragma unroll
    for (int i = 1; i < BWARPS; i++) {
        kmax = fmaxf(kmax, redmx[i]);
        kmin = fminf(kmin, redmn[i]);
    }

    int gw = slice * BWARPS + w;     // 0..63
    for (int i = gw; i < SS; i += NSLICE * BWARPS) {
        float q  = qp[i];
        float qc = q * LOG2E;
        float mc = qc * (q >= 0.f ? kmax : kmin);   // log2-domain max bound
        float num = 0.f, den = 0.f;
        #pragma unroll 4
        for (int j = lane; j <= i; j += 32) {
            float e;
            float tt = fmaf(qc, sk[j], -mc);
            asm("ex2.approx.f32 %0, %1;" : "=f"(e) : "f"(tt));
            den += e;
            num = fmaf(e, sv[j], num);
        }
        #pragma unroll
        for (int off = 16; off; off >>= 1) {
            num += __shfl_xor_sync(0xffffffffu, num, off);
            den += __shfl_xor_sync(0xffffffffu, den, off);
        }
        if (lane == 0) gatt[pair * SS + i] = num / den;
    }
}

// ---------------------------------------------------------------------------
// Kernel C: out = att @ w_out + b_out.  One thread per (b,s) row.
// att is pair-major [B*H][S] -> coalesced reads per fixed h across lanes.
// ---------------------------------------------------------------------------
__global__ void out_kernel(const float* __restrict__ gatt,
                           const float* __restrict__ w,    // [16,16] row-major
                           const float* __restrict__ bias, // [16]
                           float* __restrict__ out)
{
    __shared__ float sw[DD * DD];
    __shared__ float sb[DD];
    int t = threadIdx.x;
    if (t < DD * DD) sw[t] = w[t];
    if (t < DD)      sb[t] = bias[t];
    __syncthreads();

    int r = blockIdx.x * blockDim.x + t;
    if (r >= BB * SS) return;
    int b = r >> 11;
    int s = r & (SS - 1);

    float a[DD];
    #pragma unroll
    for (int h = 0; h < DD; h++)
        a[h] = gatt[(b * DD + h) * SS + s];

    float o[DD];
    #pragma unroll
    for (int d = 0; d < DD; d++) {
        float acc = sb[d];
        #pragma unroll
        for (int h = 0; h < DD; h++)
            acc = fmaf(a[h], sw[h * DD + d], acc);
        o[d] = acc;
    }
    float4* op = reinterpret_cast<float4*>(out + r * DD);
    #pragma unroll
    for (int q4 = 0; q4 < 4; q4++)
        op[q4] = make_float4(o[q4*4+0], o[q4*4+1], o[q4*4+2], o[q4*4+3]);
}

// ---------------------------------------------------------------------------
extern "C" void kernel_launch(void* const* d_in, const int* in_sizes, int n_in,
                              void* d_out, int out_size)
{
    const float* x     = (const float*)d_in[0];
    const float* w_qkv = (const float*)d_in[1];
    const float* b_qkv = (const float*)d_in[2];
    const float* w_out = (const float*)d_in[3];
    const float* b_out = (const float*)d_in[4];
    float* out = (float*)d_out;

    float *gq, *gk, *gv, *gatt;
    cudaGetSymbolAddress((void**)&gq,   g_q);
    cudaGetSymbolAddress((void**)&gk,   g_k);
    cudaGetSymbolAddress((void**)&gv,   g_v);
    cudaGetSymbolAddress((void**)&gatt, g_att);

    qkv_kernel<<<(BB * SS) / 256, 256>>>(x, w_qkv, b_qkv);
    attn_kernel<<<dim3(NPAIR, NSLICE), 256>>>(gq, gk, gv, gatt);
    out_kernel<<<(BB * SS) / 256, 256>>>(gatt, w_out, b_out, out);
}

// round 2
// speedup vs baseline: 1.1740x; 1.1740x over previous
#include <cuda_runtime.h>
#include <cuda_bf16.h>

// Problem constants (B=4, S=2048, D=16, HEADS=16, HEAD_SIZE=1)
#define BB   4
#define SS   2048
#define DD   16
#define NPAIR (BB * DD)          // 64 (b,h) pairs
#define LOG2E 1.4426950408889634f

// Scratch (allocation-free rule: __device__ globals)
__device__ float g_q[NPAIR * SS];
__device__ float g_k[NPAIR * SS];
__device__ float g_v[NPAIR * SS];
__device__ float g_att[NPAIR * SS];

// ---------------------------------------------------------------------------
// Kernel A: qkv = x @ w_qkv + b_qkv, scattered into pair-major q/k/v arrays.
// 4-way column split: sub = blockIdx.x>>5 handles cols [sub*12, sub*12+12).
// 128 blocks x 256 threads. Weights in SMEM, float4 broadcast loads.
// ---------------------------------------------------------------------------
__global__ void qkv_kernel(const float* __restrict__ x,
                           const float* __restrict__ w,    // [16, 48] row-major
                           const float* __restrict__ bias) // [48]
{
    __shared__ float sw[DD * 3 * DD];   // 768
    __shared__ float sb[3 * DD];        // 48
    int t = threadIdx.x;
    for (int i = t; i < DD * 3 * DD; i += blockDim.x) sw[i] = w[i];
    if (t < 3 * DD) sb[t] = bias[t];
    __syncthreads();

    int sub = blockIdx.x >> 5;                    // 0..3
    int c0  = sub * 12;
    int r   = ((blockIdx.x & 31) << 8) + t;       // 0..8191
    int b = r >> 11;
    int s = r & (SS - 1);

    float xr[DD];
    const float4* xp = reinterpret_cast<const float4*>(x + r * DD);
    #pragma unroll
    for (int q4 = 0; q4 < 4; q4++) {
        float4 v4 = xp[q4];
        xr[q4 * 4 + 0] = v4.x; xr[q4 * 4 + 1] = v4.y;
        xr[q4 * 4 + 2] = v4.z; xr[q4 * 4 + 3] = v4.w;
    }

    float acc[12];
    #pragma unroll
    for (int cc = 0; cc < 12; cc++) acc[cc] = sb[c0 + cc];

    #pragma unroll
    for (int d = 0; d < DD; d++) {
        float xd = xr[d];
        #pragma unroll
        for (int g = 0; g < 3; g++) {
            float4 w4 = *reinterpret_cast<const float4*>(&sw[d * 3 * DD + c0 + 4 * g]);
            acc[4*g+0] = fmaf(xd, w4.x, acc[4*g+0]);
            acc[4*g+1] = fmaf(xd, w4.y, acc[4*g+1]);
            acc[4*g+2] = fmaf(xd, w4.z, acc[4*g+2]);
            acc[4*g+3] = fmaf(xd, w4.w, acc[4*g+3]);
        }
    }

    #pragma unroll
    for (int cc = 0; cc < 12; cc++) {
        int c = c0 + cc;
        int pair = b * DD + (c & (DD - 1));
        float val = acc[cc];
        if (c < DD)           g_q[pair * SS + s] = val;
        else if (c < 2 * DD)  g_k[pair * SS + s] = val;
        else                  g_v[pair * SS + s] = val;
    }
}

// ---------------------------------------------------------------------------
// Kernel B: scalar-head causal attention per (b,h) pair.
// grid (64 pairs, 8 slices), 256 threads (8 warps). Global warp gw = slice*8+w
// handles row-PAIRS (2m, 2m+1) for m = gw + 64t, t=0..15.
// k,v packed as float2 in SMEM; 1 LDS.64 feeds 2 exps.
// ---------------------------------------------------------------------------
#define NSLICE 8
#define BWARPS 8

__global__ void attn_kernel(const float* __restrict__ gq,
                            const float* __restrict__ gk,
                            const float* __restrict__ gv,
                            float* __restrict__ gatt)
{
    __shared__ float2 skv[SS];
    __shared__ float redmx[BWARPS], redmn[BWARPS];

    int pair  = blockIdx.x;
    int slice = blockIdx.y;
    int t = threadIdx.x, lane = t & 31, w = t >> 5;

    const float* kp = gk + pair * SS;
    const float* vp = gv + pair * SS;
    const float* qp = gq + pair * SS;

    float lmax = -3.4e38f, lmin = 3.4e38f;
    for (int j = t; j < SS; j += 256) {
        float kv = kp[j];
        skv[j] = make_float2(kv, vp[j]);
        lmax = fmaxf(lmax, kv);
        lmin = fminf(lmin, kv);
    }
    #pragma unroll
    for (int off = 16; off; off >>= 1) {
        lmax = fmaxf(lmax, __shfl_xor_sync(0xffffffffu, lmax, off));
        lmin = fminf(lmin, __shfl_xor_sync(0xffffffffu, lmin, off));
    }
    if (lane == 0) { redmx[w] = lmax; redmn[w] = lmin; }
    __syncthreads();

    float kmax = redmx[0], kmin = redmn[0];
    #pragma unroll
    for (int i = 1; i < BWARPS; i++) {
        kmax = fmaxf(kmax, redmx[i]);
        kmin = fminf(kmin, redmn[i]);
    }

    int gw = slice * BWARPS + w;     // 0..63
    #pragma unroll 1
    for (int tt = 0; tt < SS / (2 * NSLICE * BWARPS); tt++) {
        int m  = gw + (NSLICE * BWARPS) * tt;    // 0..1023
        int i0 = 2 * m;
        int i1 = i0 + 1;

        float q0 = qp[i0], q1 = qp[i1];
        float qc0 = q0 * LOG2E, qc1 = q1 * LOG2E;
        float mc0 = qc0 * (q0 >= 0.f ? kmax : kmin);
        float mc1 = qc1 * (q1 >= 0.f ? kmax : kmin);

        float num0 = 0.f, den0 = 0.f, num1 = 0.f, den1 = 0.f;
        #pragma unroll 4
        for (int j = lane; j <= i0; j += 32) {
            float2 kv = skv[j];
            float e0, e1;
            float a0 = fmaf(qc0, kv.x, -mc0);
            float a1 = fmaf(qc1, kv.x, -mc1);
            asm("ex2.approx.f32 %0, %1;" : "=f"(e0) : "f"(a0));
            asm("ex2.approx.f32 %0, %1;" : "=f"(e1) : "f"(a1));
            den0 += e0; num0 = fmaf(e0, kv.y, num0);
            den1 += e1; num1 = fmaf(e1, kv.y, num1);
        }
        if (lane == 0) {    // the extra causal element j = i1 for row i1
            float2 kv = skv[i1];
            float e1;
            float a1 = fmaf(qc1, kv.x, -mc1);
            asm("ex2.approx.f32 %0, %1;" : "=f"(e1) : "f"(a1));
            den1 += e1; num1 = fmaf(e1, kv.y, num1);
        }
        #pragma unroll
        for (int off = 16; off; off >>= 1) {
            num0 += __shfl_xor_sync(0xffffffffu, num0, off);
            den0 += __shfl_xor_sync(0xffffffffu, den0, off);
            num1 += __shfl_xor_sync(0xffffffffu, num1, off);
            den1 += __shfl_xor_sync(0xffffffffu, den1, off);
        }
        if (lane == 0) {
            gatt[pair * SS + i0] = __fdividef(num0, den0);
            gatt[pair * SS + i1] = __fdividef(num1, den1);
        }
    }
}

// ---------------------------------------------------------------------------
// Kernel C: out = att @ w_out + b_out.  4-way column split like kernel A:
// sub handles output cols [sub*4, sub*4+4). 128 blocks x 256 threads.
// ---------------------------------------------------------------------------
__global__ void out_kernel(const float* __restrict__ gatt,
                           const float* __restrict__ w,    // [16,16] row-major
                           const float* __restrict__ bias, // [16]
                           float* __restrict__ out)
{
    __shared__ float sw[DD * DD];
    __shared__ float sb[DD];
    int t = threadIdx.x;
    if (t < DD * DD) sw[t] = w[t];
    if (t < DD)      sb[t] = bias[t];
    __syncthreads();

    int sub = blockIdx.x >> 5;                 // 0..3
    int d0  = sub * 4;
    int r   = ((blockIdx.x & 31) << 8) + t;
    int b = r >> 11;
    int s = r & (SS - 1);

    float acc0 = sb[d0+0], acc1 = sb[d0+1], acc2 = sb[d0+2], acc3 = sb[d0+3];
    #pragma unroll
    for (int h = 0; h < DD; h++) {
        float a = gatt[(b * DD + h) * SS + s];
        float4 w4 = *reinterpret_cast<const float4*>(&sw[h * DD + d0]);
        acc0 = fmaf(a, w4.x, acc0);
        acc1 = fmaf(a, w4.y, acc1);
        acc2 = fmaf(a, w4.z, acc2);
        acc3 = fmaf(a, w4.w, acc3);
    }
    *reinterpret_cast<float4*>(out + r * DD + d0) = make_float4(acc0, acc1, acc2, acc3);
}

// ---------------------------------------------------------------------------
extern "C" void kernel_launch(void* const* d_in, const int* in_sizes, int n_in,
                              void* d_out, int out_size)
{
    const float* x     = (const float*)d_in[0];
    const float* w_qkv = (const float*)d_in[1];
    const float* b_qkv = (const float*)d_in[2];
    const float* w_out = (const float*)d_in[3];
    const float* b_out = (const float*)d_in[4];
    float* out = (float*)d_out;

    float *gq, *gk, *gv, *gatt;
    cudaGetSymbolAddress((void**)&gq,   g_q);
    cudaGetSymbolAddress((void**)&gk,   g_k);
    cudaGetSymbolAddress((void**)&gv,   g_v);
    cudaGetSymbolAddress((void**)&gatt, g_att);

    qkv_kernel<<<128, 256>>>(x, w_qkv, b_qkv);
    attn_kernel<<<dim3(NPAIR, NSLICE), 256>>>(gq, gk, gv, gatt);
    out_kernel<<<128, 256>>>(gatt, w_out, b_out, out);
}

// round 4
// speedup vs baseline: 1.2845x; 1.0941x over previous
#include <cuda_runtime.h>
#include <cuda_bf16.h>
#include <cstdint>

// Problem constants (B=4, S=2048, D=16, HEADS=16, HEAD_SIZE=1)
#define BB   4
#define SS   2048
#define DD   16
#define NPAIR (BB * DD)          // 64 (b,h) pairs
#define LOG2E 1.4426950408889634f

// Scratch (allocation-free rule: __device__ globals)
__device__ float  g_q [NPAIR * SS];
__device__ float4 g_kv[NPAIR * SS];      // (k, k, v, v) packed per (pair, s)
__device__ float  g_att[BB * SS * DD];   // [b][s][h] layout

// ---------------------------------------------------------------------------
// Kernel A: qkv = x @ w_qkv + b_qkv.
// 12-way column split (4 cols per thread, aligned to q/k/v boundaries).
// grid 384 = 32 row-blocks x 12 col-groups, 256 threads.
// q -> g_q pair-major; k -> g_kv.xy as (k,k); v -> g_kv.zw as (v,v).
// ---------------------------------------------------------------------------
__global__ void qkv_kernel(const float* __restrict__ x,
                           const float* __restrict__ w,    // [16, 48] row-major
                           const float* __restrict__ bias) // [48]
{
    __shared__ float sw[DD * 3 * DD];   // 768
    __shared__ float sb[3 * DD];        // 48
    int t = threadIdx.x;
    for (int i = t; i < DD * 3 * DD; i += blockDim.x) sw[i] = w[i];
    if (t < 3 * DD) sb[t] = bias[t];
    __syncthreads();

    int grp = blockIdx.x % 12;                    // column group 0..11
    int c0  = grp * 4;
    int r   = (blockIdx.x / 12) * 256 + t;        // 0..8191
    int b = r >> 11;
    int s = r & (SS - 1);

    float xr[DD];
    const float4* xp = reinterpret_cast<const float4*>(x + r * DD);
    #pragma unroll
    for (int q4 = 0; q4 < 4; q4++) {
        float4 v4 = xp[q4];
        xr[q4 * 4 + 0] = v4.x; xr[q4 * 4 + 1] = v4.y;
        xr[q4 * 4 + 2] = v4.z; xr[q4 * 4 + 3] = v4.w;
    }

    float acc0 = sb[c0+0], acc1 = sb[c0+1], acc2 = sb[c0+2], acc3 = sb[c0+3];
    #pragma unroll
    for (int d = 0; d < DD; d++) {
        float xd = xr[d];
        float4 w4 = *reinterpret_cast<const float4*>(&sw[d * 3 * DD + c0]);
        acc0 = fmaf(xd, w4.x, acc0);
        acc1 = fmaf(xd, w4.y, acc1);
        acc2 = fmaf(xd, w4.z, acc2);
        acc3 = fmaf(xd, w4.w, acc3);
    }

    float acc[4] = {acc0, acc1, acc2, acc3};
    #pragma unroll
    for (int cc = 0; cc < 4; cc++) {
        int c = c0 + cc;
        int h = c & (DD - 1);
        int pair = b * DD + h;
        float val = acc[cc];
        if (c < DD) {
            g_q[pair * SS + s] = val;
        } else if (c < 2 * DD) {
            *reinterpret_cast<float2*>(&g_kv[pair * SS + s].x) = make_float2(val, val);
        } else {
            *reinterpret_cast<float2*>(&g_kv[pair * SS + s].z) = make_float2(val, val);
        }
    }
}

// ---------------------------------------------------------------------------
// Kernel B: scalar-head causal attention.
// grid 444 = 148*3 blocks (one exact wave, 3 blocks/SM), 256 threads (8 warps).
// Block bid: pair = bid % 64, rep = bid / 64. Pairs 0-59 have 7 reps, 60-63
// have 6. Warp gw = rep*8 + w handles row-pairs m = gw, gw+R*8, ...
// Inner loop: packed f32x2 math, 2 exps per ~7 issue slots -> MUFU-bound.
// ---------------------------------------------------------------------------
__global__ void __launch_bounds__(256) attn_kernel(const float* __restrict__ gq,
                            const float4* __restrict__ gkv,
                            float* __restrict__ gatt)
{
    __shared__ float4 skv[SS];           // 32KB: (k,k,v,v)
    __shared__ float redmx[8], redmn[8];

    int bid  = blockIdx.x;
    int pair = bid & 63;
    int rep  = bid >> 6;                 // 0..6
    int R    = (pair < 60) ? 7 : 6;      // reps for this pair

    int t = threadIdx.x, lane = t & 31, w = t >> 5;

    const float4* kvp = gkv + pair * SS;
    const float*  qp  = gq  + pair * SS;

    float lmax = -3.4e38f, lmin = 3.4e38f;
    for (int j = t; j < SS; j += 256) {
        float4 kv = kvp[j];
        skv[j] = kv;
        lmax = fmaxf(lmax, kv.x);
        lmin = fminf(lmin, kv.x);
    }
    #pragma unroll
    for (int off = 16; off; off >>= 1) {
        lmax = fmaxf(lmax, __shfl_xor_sync(0xffffffffu, lmax, off));
        lmin = fminf(lmin, __shfl_xor_sync(0xffffffffu, lmin, off));
    }
    if (lane == 0) { redmx[w] = lmax; redmn[w] = lmin; }
    __syncthreads();

    float kmax = redmx[0], kmin = redmn[0];
    #pragma unroll
    for (int i = 1; i < 8; i++) {
        kmax = fmaxf(kmax, redmx[i]);
        kmin = fminf(kmin, redmn[i]);
    }

    // u32 SMEM address of skv for ld.shared
    uint32_t sbase;
    asm("{ .reg .u64 tmp; cvta.to.shared.u64 tmp, %1; cvt.u32.u64 %0, tmp; }"
        : "=r"(sbase) : "l"(skv));

    int b_idx = pair >> 4;
    int h_idx = pair & 15;
    float* gout = gatt + (b_idx * SS) * DD + h_idx;   // + i*DD per row

    int gw   = rep * 8 + w;        // 0 .. R*8-1
    int step = R * 8;

    for (int m = gw; m < SS / 2; m += step) {
        int i0 = 2 * m;
        int i1 = i0 + 1;

        float q0 = qp[i0], q1 = qp[i1];
        float qc0 = q0 * LOG2E, qc1 = q1 * LOG2E;
        float nmc0 = -qc0 * (q0 >= 0.f ? kmax : kmin);
        float nmc1 = -qc1 * (q1 >= 0.f ? kmax : kmin);

        unsigned long long qc01, nmc01, num01 = 0ull, den01 = 0ull;
        asm("mov.b64 %0, {%1,%2};" : "=l"(qc01)  : "f"(qc0),  "f"(qc1));
        asm("mov.b64 %0, {%1,%2};" : "=l"(nmc01) : "f"(nmc0), "f"(nmc1));

        #pragma unroll 4
        for (int j = lane; j <= i0; j += 32) {
            unsigned long long kk, vv, a01, e01;
            uint32_t addr = sbase + (uint32_t)j * 16u;
            asm("ld.shared.v2.u64 {%0,%1}, [%2];" : "=l"(kk), "=l"(vv) : "r"(addr));
            asm("fma.rn.f32x2 %0, %1, %2, %3;" : "=l"(a01)
                : "l"(qc01), "l"(kk), "l"(nmc01));
            float a0, a1, e0, e1;
            asm("mov.b64 {%0,%1}, %2;" : "=f"(a0), "=f"(a1) : "l"(a01));
            asm("ex2.approx.f32 %0, %1;" : "=f"(e0) : "f"(a0));
            asm("ex2.approx.f32 %0, %1;" : "=f"(e1) : "f"(a1));
            asm("mov.b64 %0, {%1,%2};" : "=l"(e01) : "f"(e0), "f"(e1));
            asm("add.rn.f32x2 %0, %0, %1;" : "+l"(den01) : "l"(e01));
            asm("fma.rn.f32x2 %0, %1, %2, %0;" : "+l"(num01) : "l"(e01), "l"(vv));
        }

        float num0, num1, den0, den1;
        asm("mov.b64 {%0,%1}, %2;" : "=f"(num0), "=f"(num1) : "l"(num01));
        asm("mov.b64 {%0,%1}, %2;" : "=f"(den0), "=f"(den1) : "l"(den01));

        if (lane == 0) {   // causal extra element j = i1 for row i1
            float4 kv = skv[i1];
            float e1;
            float a1 = fmaf(qc1, kv.x, nmc1);
            asm("ex2.approx.f32 %0, %1;" : "=f"(e1) : "f"(a1));
            den1 += e1; num1 = fmaf(e1, kv.z, num1);
        }
        #pragma unroll
        for (int off = 16; off; off >>= 1) {
            num0 += __shfl_xor_sync(0xffffffffu, num0, off);
            den0 += __shfl_xor_sync(0xffffffffu, den0, off);
            num1 += __shfl_xor_sync(0xffffffffu, num1, off);
            den1 += __shfl_xor_sync(0xffffffffu, den1, off);
        }
        if (lane == 0) {
            gout[i0 * DD] = __fdividef(num0, den0);
            gout[i1 * DD] = __fdividef(num1, den1);
        }
    }
}

// ---------------------------------------------------------------------------
// Kernel C: out = att @ w_out + b_out.  att is [b][s][h] -> 4 contiguous
// LDG.128 per row. 4-way output-column split: 128 blocks x 256 threads.
// ---------------------------------------------------------------------------
__global__ void out_kernel(const float* __restrict__ gatt,
                           const float* __restrict__ w,    // [16,16] row-major
                           const float* __restrict__ bias, // [16]
                           float* __restrict__ out)
{
    __shared__ float sw[DD * DD];
    __shared__ float sb[DD];
    int t = threadIdx.x;
    if (t < DD * DD) sw[t] = w[t];
    if (t < DD)      sb[t] = bias[t];
    __syncthreads();

    int sub = blockIdx.x >> 5;                 // 0..3
    int d0  = sub * 4;
    int r   = ((blockIdx.x & 31) << 8) + t;    // (b,s) row

    float a[DD];
    const float4* ap = reinterpret_cast<const float4*>(gatt + r * DD);
    #pragma unroll
    for (int q4 = 0; q4 < 4; q4++) {
        float4 v4 = ap[q4];
        a[q4*4+0] = v4.x; a[q4*4+1] = v4.y; a[q4*4+2] = v4.z; a[q4*4+3] = v4.w;
    }

    float acc0 = sb[d0+0], acc1 = sb[d0+1], acc2 = sb[d0+2], acc3 = sb[d0+3];
    #pragma unroll
    for (int h = 0; h < DD; h++) {
        float4 w4 = *reinterpret_cast<const float4*>(&sw[h * DD + d0]);
        acc0 = fmaf(a[h], w4.x, acc0);
        acc1 = fmaf(a[h], w4.y, acc1);
        acc2 = fmaf(a[h], w4.z, acc2);
        acc3 = fmaf(a[h], w4.w, acc3);
    }
    *reinterpret_cast<float4*>(out + r * DD + d0) = make_float4(acc0, acc1, acc2, acc3);
}

// ---------------------------------------------------------------------------
extern "C" void kernel_launch(void* const* d_in, const int* in_sizes, int n_in,
                              void* d_out, int out_size)
{
    const float* x     = (const float*)d_in[0];
    const float* w_qkv = (const float*)d_in[1];
    const float* b_qkv = (const float*)d_in[2];
    const float* w_out = (const float*)d_in[3];
    const float* b_out = (const float*)d_in[4];
    float* out = (float*)d_out;

    float  *gq, *gatt;
    float4 *gkv;
    cudaGetSymbolAddress((void**)&gq,   g_q);
    cudaGetSymbolAddress((void**)&gkv,  g_kv);
    cudaGetSymbolAddress((void**)&gatt, g_att);

    qkv_kernel<<<384, 256>>>(x, w_qkv, b_qkv);
    attn_kernel<<<444, 256>>>(gq, gkv, gatt);
    out_kernel<<<128, 256>>>(gatt, w_out, b_out, out);
}

// round 5
// speedup vs baseline: 1.3432x; 1.0457x over previous
#include <cuda_runtime.h>
#include <cuda_bf16.h>
#include <cstdint>

// Problem constants (B=4, S=2048, D=16, HEADS=16, HEAD_SIZE=1)
#define BB   4
#define SS   2048
#define DD   16
#define NPAIR (BB * DD)          // 64 (b,h) pairs
#define LOG2E 1.4426950408889634f

// Scratch (allocation-free rule: __device__ global)
__device__ float g_att[BB * SS * DD];   // [b][s][h] layout

// ---------------------------------------------------------------------------
// Kernel 1: fused QKV-projection + scalar-head causal attention.
// grid 444 = 148*3 (one exact wave, 3 blocks/SM), 256 threads (8 warps).
// Block bid: pair = bid & 63, rep = bid >> 6. Pairs 0-59: 7 reps, 60-63: 6.
// Prologue: block computes q/k/v for ALL 2048 rows of its (b,h) pair from x
// (x rows come from L2 after the first touch), storing q and (k,v) in SMEM.
// Main loop: warp gw handles row-pairs (2m, 2m+1); scalar FFMA/MUFU/FADD,
// one LDS.64 per 2 exps -> SMEM crossbar at 50% of MUFU, MUFU-bound.
// ---------------------------------------------------------------------------
__global__ void __launch_bounds__(256) attn_fused_kernel(
    const float* __restrict__ x,      // [B, S, D]
    const float* __restrict__ w,      // [16, 48] row-major
    const float* __restrict__ bias,   // [48]
    float* __restrict__ gatt)         // [b][s][h]
{
    __shared__ float2 skv[SS];        // 16KB: (k, v) per row
    __shared__ float  sq [SS];        // 8KB: q per row
    __shared__ float  swq[DD], swk[DD], swv[DD];
    __shared__ float  sbias[3];
    __shared__ float  redmx[8], redmn[8];

    int bid  = blockIdx.x;
    int pair = bid & 63;
    int rep  = bid >> 6;                 // 0..6
    int R    = (pair < 60) ? 7 : 6;

    int t = threadIdx.x, lane = t & 31, wrp = t >> 5;
    int b_idx = pair >> 4;
    int h_idx = pair & 15;

    // --- load this head's weight columns into SMEM ---
    if (t < DD) {
        swq[t] = w[t * 48 + h_idx];
        swk[t] = w[t * 48 + 16 + h_idx];
        swv[t] = w[t * 48 + 32 + h_idx];
    }
    if (t < 3) sbias[t] = bias[t * 16 + h_idx];
    __syncthreads();

    float bq = sbias[0], bk = sbias[1], bv = sbias[2];

    // --- prologue: compute q/k/v for all rows of this (b, h) pair ---
    float lmax = -3.4e38f, lmin = 3.4e38f;
    const float4* xbase = reinterpret_cast<const float4*>(x + (size_t)b_idx * SS * DD);
    #pragma unroll
    for (int it = 0; it < SS / 256; it++) {
        int j = t + 256 * it;
        float xr[DD];
        #pragma unroll
        for (int q4 = 0; q4 < 4; q4++) {
            float4 v4 = xbase[j * 4 + q4];
            xr[q4*4+0] = v4.x; xr[q4*4+1] = v4.y;
            xr[q4*4+2] = v4.z; xr[q4*4+3] = v4.w;
        }
        float aq = bq, ak = bk, av = bv;
        #pragma unroll
        for (int d = 0; d < DD; d++) {
            float xd = xr[d];
            aq = fmaf(xd, swq[d], aq);
            ak = fmaf(xd, swk[d], ak);
            av = fmaf(xd, swv[d], av);
        }
        skv[j] = make_float2(ak, av);
        sq[j]  = aq;
        lmax = fmaxf(lmax, ak);
        lmin = fminf(lmin, ak);
    }

    // --- block-wide k max/min (for stable softmax bound) ---
    #pragma unroll
    for (int off = 16; off; off >>= 1) {
        lmax = fmaxf(lmax, __shfl_xor_sync(0xffffffffu, lmax, off));
        lmin = fminf(lmin, __shfl_xor_sync(0xffffffffu, lmin, off));
    }
    if (lane == 0) { redmx[wrp] = lmax; redmn[wrp] = lmin; }
    __syncthreads();

    float kmax = redmx[0], kmin = redmn[0];
    #pragma unroll
    for (int i = 1; i < 8; i++) {
        kmax = fmaxf(kmax, redmx[i]);
        kmin = fminf(kmin, redmn[i]);
    }

    uint32_t sbase;
    asm("{ .reg .u64 tmp; cvta.to.shared.u64 tmp, %1; cvt.u32.u64 %0, tmp; }"
        : "=r"(sbase) : "l"(skv));

    float* gout = gatt + (size_t)(b_idx * SS) * DD + h_idx;   // + i*DD per row

    int gw   = rep * 8 + wrp;      // 0 .. R*8-1
    int step = R * 8;

    for (int m = gw; m < SS / 2; m += step) {
        int i0 = 2 * m;
        int i1 = i0 + 1;

        float q0 = sq[i0], q1 = sq[i1];
        float qc0 = q0 * LOG2E, qc1 = q1 * LOG2E;
        float nmc0 = -qc0 * (q0 >= 0.f ? kmax : kmin);
        float nmc1 = -qc1 * (q1 >= 0.f ? kmax : kmin);

        float num0 = 0.f, den0 = 0.f, num1 = 0.f, den1 = 0.f;

        #pragma unroll 4
        for (int j = lane; j <= i0; j += 32) {
            float kj, vj;
            uint32_t addr = sbase + (uint32_t)j * 8u;
            asm("ld.shared.v2.f32 {%0,%1}, [%2];" : "=f"(kj), "=f"(vj) : "r"(addr));
            float a0 = fmaf(qc0, kj, nmc0);
            float a1 = fmaf(qc1, kj, nmc1);
            float e0, e1;
            asm("ex2.approx.f32 %0, %1;" : "=f"(e0) : "f"(a0));
            asm("ex2.approx.f32 %0, %1;" : "=f"(e1) : "f"(a1));
            den0 += e0;
            den1 += e1;
            num0 = fmaf(e0, vj, num0);
            num1 = fmaf(e1, vj, num1);
        }

        if (lane == 0) {   // causal extra element j = i1 for row i1
            float2 kv = skv[i1];
            float e1;
            float a1 = fmaf(qc1, kv.x, nmc1);
            asm("ex2.approx.f32 %0, %1;" : "=f"(e1) : "f"(a1));
            den1 += e1; num1 = fmaf(e1, kv.y, num1);
        }
        #pragma unroll
        for (int off = 16; off; off >>= 1) {
            num0 += __shfl_xor_sync(0xffffffffu, num0, off);
            den0 += __shfl_xor_sync(0xffffffffu, den0, off);
            num1 += __shfl_xor_sync(0xffffffffu, num1, off);
            den1 += __shfl_xor_sync(0xffffffffu, den1, off);
        }
        if (lane == 0) {
            gout[i0 * DD] = __fdividef(num0, den0);
            gout[i1 * DD] = __fdividef(num1, den1);
        }
    }
}

// ---------------------------------------------------------------------------
// Kernel 2: out = att @ w_out + b_out.  att is [b][s][h] -> 4 contiguous
// LDG.128 per row. 4-way output-column split: 128 blocks x 256 threads.
// ---------------------------------------------------------------------------
__global__ void out_kernel(const float* __restrict__ gatt,
                           const float* __restrict__ w,    // [16,16] row-major
                           const float* __restrict__ bias, // [16]
                           float* __restrict__ out)
{
    __shared__ float sw[DD * DD];
    __shared__ float sb[DD];
    int t = threadIdx.x;
    if (t < DD * DD) sw[t] = w[t];
    if (t < DD)      sb[t] = bias[t];
    __syncthreads();

    int sub = blockIdx.x >> 5;                 // 0..3
    int d0  = sub * 4;
    int r   = ((blockIdx.x & 31) << 8) + t;    // (b,s) row

    float a[DD];
    const float4* ap = reinterpret_cast<const float4*>(gatt + (size_t)r * DD);
    #pragma unroll
    for (int q4 = 0; q4 < 4; q4++) {
        float4 v4 = ap[q4];
        a[q4*4+0] = v4.x; a[q4*4+1] = v4.y; a[q4*4+2] = v4.z; a[q4*4+3] = v4.w;
    }

    float acc0 = sb[d0+0], acc1 = sb[d0+1], acc2 = sb[d0+2], acc3 = sb[d0+3];
    #pragma unroll
    for (int h = 0; h < DD; h++) {
        float4 w4 = *reinterpret_cast<const float4*>(&sw[h * DD + d0]);
        acc0 = fmaf(a[h], w4.x, acc0);
        acc1 = fmaf(a[h], w4.y, acc1);
        acc2 = fmaf(a[h], w4.z, acc2);
        acc3 = fmaf(a[h], w4.w, acc3);
    }
    *reinterpret_cast<float4*>(out + (size_t)r * DD + d0) =
        make_float4(acc0, acc1, acc2, acc3);
}

// ---------------------------------------------------------------------------
extern "C" void kernel_launch(void* const* d_in, const int* in_sizes, int n_in,
                              void* d_out, int out_size)
{
    const float* x     = (const float*)d_in[0];
    const float* w_qkv = (const float*)d_in[1];
    const float* b_qkv = (const float*)d_in[2];
    const float* w_out = (const float*)d_in[3];
    const float* b_out = (const float*)d_in[4];
    float* out = (float*)d_out;

    float* gatt;
    cudaGetSymbolAddress((void**)&gatt, g_att);

    attn_fused_kernel<<<444, 256>>>(x, w_qkv, b_qkv, gatt);
    out_kernel<<<128, 256>>>(gatt, w_out, b_out, out);
}